// round 1
// baseline (speedup 1.0000x reference)
#include <cuda_runtime.h>
#include <math.h>

// Problem constants (fixed shapes per reference)
#define D   32      // latent dim
#define HH  64      // hidden
#define BB  8192    // batch
#define TT  256     // time steps
#define MT  64      // batch rows per CTA  (128 CTAs * 64 = 8192 exactly)
#define ZS  68      // row stride (floats) for transposed Z  [D][MT+pad]
#define HS  68      // row stride (floats) for transposed H  [H][MT+pad]

// Shared layout (float offsets)
//  sW1: 33*64 = 2112   @ 0
//  sW2: 64*64 = 4096   @ 2112
//  sW3: 64*32 = 2048   @ 6208
//  sb1: 64             @ 8256
//  sb2: 64             @ 8320
//  sb3: 32             @ 8384
//  sstd: 32            @ 8416
//  sTs: 256            @ 8448
//  sZ : 32*68 = 2176   @ 8704
//  sH1: 64*68 = 4352   @ 10880
//  sH2: 64*68 = 4352   @ 15232
//  total 19584 floats = 78336 bytes
#define SMEM_FLOATS 19584

__global__ __launch_bounds__(256, 1)
void sde_kernel(const float* __restrict__ z0,
                const float* __restrict__ ts,
                const float* __restrict__ dW,
                const float* __restrict__ W1, const float* __restrict__ b1,
                const float* __restrict__ W2, const float* __restrict__ b2,
                const float* __restrict__ W3, const float* __restrict__ b3,
                const float* __restrict__ logstd,
                float* __restrict__ out)
{
    extern __shared__ float sm[];
    float* sW1 = sm;
    float* sW2 = sm + 2112;
    float* sW3 = sm + 6208;
    float* sb1 = sm + 8256;
    float* sb2 = sm + 8320;
    float* sb3 = sm + 8384;
    float* sstd = sm + 8416;
    float* sTs = sm + 8448;
    float* sZ  = sm + 8704;
    float* sH1 = sm + 10880;
    float* sH2 = sm + 15232;

    const int tid = threadIdx.x;
    const int tx = tid & 15;        // output-column block (16 blocks)
    const int ty = tid >> 4;        // row block (16 blocks of 4 rows)
    const int m0 = ty * 4;
    const int j0 = tx * 4;          // GEMM1/2: 4 cols per thread
    const int d0 = tx * 2;          // GEMM3: 2 cols per thread
    const int base = blockIdx.x * MT;

    // ---- one-time parameter staging ----
    for (int i = tid; i < 33 * HH; i += 256) sW1[i] = W1[i];
    for (int i = tid; i < HH * HH; i += 256) sW2[i] = W2[i];
    for (int i = tid; i < HH * D;  i += 256) sW3[i] = W3[i];
    if (tid < HH) { sb1[tid] = b1[tid]; sb2[tid] = b2[tid]; }
    if (tid < D)  { sb3[tid] = b3[tid]; sstd[tid] = expf(logstd[tid]); }
    sTs[tid] = ts[tid];   // TT == 256 == blockDim

    // ---- z0 -> sZ (feature-major) and out[0] ----
    for (int i = tid; i < MT * D; i += 256) {
        int m = i >> 5, d = i & 31;
        float v = z0[(size_t)(base + m) * D + d];
        sZ[d * ZS + m] = v;
        out[(size_t)(base + m) * D + d] = v;
    }
    __syncthreads();

    // ---- time loop (sequential; all state stays in smem) ----
    for (int t = 0; t < TT - 1; ++t) {
        const float tcur = sTs[t];
        const float dtv  = sTs[t + 1] - tcur;
        const float sq   = sqrtf(dtv);

        // prefetch this step's noise early; consumed at end of step
        float2 dwreg[4];
        {
            const float* dwp = dW + ((size_t)t * BB + base + m0) * D + d0;
            #pragma unroll
            for (int mi = 0; mi < 4; mi++)
                dwreg[mi] = *(const float2*)(dwp + (size_t)mi * D);
        }

        // ================= GEMM1: [t,z] @ W1 -> tanh -> sH1 =================
        {
            float acc[4][4];
            float4 w0 = *(const float4*)&sW1[j0];       // t-row of W1
            float4 bb = *(const float4*)&sb1[j0];
            #pragma unroll
            for (int mi = 0; mi < 4; mi++) {
                acc[mi][0] = fmaf(tcur, w0.x, bb.x);
                acc[mi][1] = fmaf(tcur, w0.y, bb.y);
                acc[mi][2] = fmaf(tcur, w0.z, bb.z);
                acc[mi][3] = fmaf(tcur, w0.w, bb.w);
            }
            #pragma unroll 8
            for (int k = 0; k < D; k++) {
                float4 a = *(const float4*)&sZ[k * ZS + m0];
                float4 b = *(const float4*)&sW1[(k + 1) * HH + j0];
                acc[0][0] = fmaf(a.x, b.x, acc[0][0]); acc[0][1] = fmaf(a.x, b.y, acc[0][1]);
                acc[0][2] = fmaf(a.x, b.z, acc[0][2]); acc[0][3] = fmaf(a.x, b.w, acc[0][3]);
                acc[1][0] = fmaf(a.y, b.x, acc[1][0]); acc[1][1] = fmaf(a.y, b.y, acc[1][1]);
                acc[1][2] = fmaf(a.y, b.z, acc[1][2]); acc[1][3] = fmaf(a.y, b.w, acc[1][3]);
                acc[2][0] = fmaf(a.z, b.x, acc[2][0]); acc[2][1] = fmaf(a.z, b.y, acc[2][1]);
                acc[2][2] = fmaf(a.z, b.z, acc[2][2]); acc[2][3] = fmaf(a.z, b.w, acc[2][3]);
                acc[3][0] = fmaf(a.w, b.x, acc[3][0]); acc[3][1] = fmaf(a.w, b.y, acc[3][1]);
                acc[3][2] = fmaf(a.w, b.z, acc[3][2]); acc[3][3] = fmaf(a.w, b.w, acc[3][3]);
            }
            #pragma unroll
            for (int ji = 0; ji < 4; ji++) {
                float4 v;
                v.x = tanhf(acc[0][ji]); v.y = tanhf(acc[1][ji]);
                v.z = tanhf(acc[2][ji]); v.w = tanhf(acc[3][ji]);
                *(float4*)&sH1[(j0 + ji) * HS + m0] = v;
            }
        }
        __syncthreads();

        // ================= GEMM2: h1 @ W2 -> tanh -> sH2 =================
        {
            float acc[4][4];
            float4 bb = *(const float4*)&sb2[j0];
            #pragma unroll
            for (int mi = 0; mi < 4; mi++) {
                acc[mi][0] = bb.x; acc[mi][1] = bb.y;
                acc[mi][2] = bb.z; acc[mi][3] = bb.w;
            }
            #pragma unroll 8
            for (int k = 0; k < HH; k++) {
                float4 a = *(const float4*)&sH1[k * HS + m0];
                float4 b = *(const float4*)&sW2[k * HH + j0];
                acc[0][0] = fmaf(a.x, b.x, acc[0][0]); acc[0][1] = fmaf(a.x, b.y, acc[0][1]);
                acc[0][2] = fmaf(a.x, b.z, acc[0][2]); acc[0][3] = fmaf(a.x, b.w, acc[0][3]);
                acc[1][0] = fmaf(a.y, b.x, acc[1][0]); acc[1][1] = fmaf(a.y, b.y, acc[1][1]);
                acc[1][2] = fmaf(a.y, b.z, acc[1][2]); acc[1][3] = fmaf(a.y, b.w, acc[1][3]);
                acc[2][0] = fmaf(a.z, b.x, acc[2][0]); acc[2][1] = fmaf(a.z, b.y, acc[2][1]);
                acc[2][2] = fmaf(a.z, b.z, acc[2][2]); acc[2][3] = fmaf(a.z, b.w, acc[2][3]);
                acc[3][0] = fmaf(a.w, b.x, acc[3][0]); acc[3][1] = fmaf(a.w, b.y, acc[3][1]);
                acc[3][2] = fmaf(a.w, b.z, acc[3][2]); acc[3][3] = fmaf(a.w, b.w, acc[3][3]);
            }
            #pragma unroll
            for (int ji = 0; ji < 4; ji++) {
                float4 v;
                v.x = tanhf(acc[0][ji]); v.y = tanhf(acc[1][ji]);
                v.z = tanhf(acc[2][ji]); v.w = tanhf(acc[3][ji]);
                *(float4*)&sH2[(j0 + ji) * HS + m0] = v;
            }
        }
        __syncthreads();

        // ========= GEMM3: h2 @ W3 + Euler-Maruyama update (fused) =========
        {
            float acc[4][2];
            float2 bb = *(const float2*)&sb3[d0];
            #pragma unroll
            for (int mi = 0; mi < 4; mi++) { acc[mi][0] = bb.x; acc[mi][1] = bb.y; }
            #pragma unroll 8
            for (int k = 0; k < HH; k++) {
                float4 a = *(const float4*)&sH2[k * HS + m0];
                float2 b = *(const float2*)&sW3[k * D + d0];
                acc[0][0] = fmaf(a.x, b.x, acc[0][0]); acc[0][1] = fmaf(a.x, b.y, acc[0][1]);
                acc[1][0] = fmaf(a.y, b.x, acc[1][0]); acc[1][1] = fmaf(a.y, b.y, acc[1][1]);
                acc[2][0] = fmaf(a.z, b.x, acc[2][0]); acc[2][1] = fmaf(a.z, b.y, acc[2][1]);
                acc[3][0] = fmaf(a.w, b.x, acc[3][0]); acc[3][1] = fmaf(a.w, b.y, acc[3][1]);
            }
            const float s0 = sstd[d0] * sq;
            const float s1 = sstd[d0 + 1] * sq;
            float* orow = out + ((size_t)(t + 1) * BB + base + m0) * D + d0;
            #pragma unroll
            for (int mi = 0; mi < 4; mi++) {
                const int m = m0 + mi;
                float zo0 = sZ[d0 * ZS + m];
                float zo1 = sZ[(d0 + 1) * ZS + m];
                float zn0 = fmaf(acc[mi][0], dtv, fmaf(s0, dwreg[mi].x, zo0));
                float zn1 = fmaf(acc[mi][1], dtv, fmaf(s1, dwreg[mi].y, zo1));
                sZ[d0 * ZS + m] = zn0;
                sZ[(d0 + 1) * ZS + m] = zn1;
                float2 o; o.x = zn0; o.y = zn1;
                *(float2*)(orow + (size_t)mi * D) = o;
            }
        }
        __syncthreads();   // sZ writes visible before next step's GEMM1
    }
}

extern "C" void kernel_launch(void* const* d_in, const int* in_sizes, int n_in,
                              void* d_out, int out_size)
{
    (void)in_sizes; (void)n_in; (void)out_size;
    const float* z0     = (const float*)d_in[0];
    const float* ts     = (const float*)d_in[1];
    const float* dW     = (const float*)d_in[2];
    const float* W1     = (const float*)d_in[3];
    const float* b1     = (const float*)d_in[4];
    const float* W2     = (const float*)d_in[5];
    const float* b2     = (const float*)d_in[6];
    const float* W3     = (const float*)d_in[7];
    const float* b3     = (const float*)d_in[8];
    const float* logstd = (const float*)d_in[9];
    float* out = (float*)d_out;

    static bool attr_set = false;  // idempotent attribute; not a work guard
    if (!attr_set) {
        cudaFuncSetAttribute(sde_kernel,
                             cudaFuncAttributeMaxDynamicSharedMemorySize,
                             SMEM_FLOATS * sizeof(float));
        attr_set = true;
    }

    sde_kernel<<<BB / MT, 256, SMEM_FLOATS * sizeof(float)>>>(
        z0, ts, dW, W1, b1, W2, b2, W3, b3, logstd, out);
}